// round 14
// baseline (speedup 1.0000x reference)
#include <cuda_runtime.h>
#include <cuda_fp16.h>
#include <math.h>

#define IN_DIM 128
#define HID    64
#define MAXN   100000
#define MAXE   1600000

typedef unsigned long long ull;

// packed dual-fp32 ops (sm_100+; SASS FFMA2 — only reachable via PTX f32x2)
#define FMA2(d, a, b, c) \
    asm("fma.rn.f32x2 %0, %1, %2, %3;" : "=l"(d) : "l"(a), "l"(b), "l"(c))
#define PACKDUP(d, v) \
    asm("mov.b64 %0, {%1, %2};" : "=l"(d) : "f"(v), "f"(v))
#define UNPACK2(lo, hi, p) \
    asm("mov.b64 {%0, %1}, %2;" : "=f"(lo), "=f"(hi) : "l"(p))

// ---------------- scratch (static device globals; no allocation) ----------------
__device__ __align__(16) float  g_h   [(size_t)MAXN * HID];  // layer input (fp32)
__device__ __align__(16) __half g_hw_h[(size_t)MAXN * HID];  // h @ W (fp16 storage)
__device__ float g_dinv[MAXN];
__device__ int   g_cnt[MAXN];        // in-degree (without self loop)
__device__ int   g_base[MAXN];       // CSR row start
__device__ int   g_cursor[MAXN];     // fill cursor
__device__ int   g_total;            // atomic allocation counter
__device__ __align__(16) int2 g_csr[MAXE];  // (src, nrm bits) per CSR slot

// ================= CSR build (scan-free: atomic row allocation) =================
__global__ void zero_cnt_kernel(int n) {
    int i = blockIdx.x * blockDim.x + threadIdx.x;
    if (i < n) g_cnt[i] = 0;
    if (i == 0) g_total = 0;
}

__global__ void hist_kernel(const int* __restrict__ dst, int E) {
    int e = blockIdx.x * blockDim.x + threadIdx.x;
    if (e < E) atomicAdd(&g_cnt[dst[e]], 1);
}

__global__ void alloc_base_kernel(int n) {
    int i = blockIdx.x * blockDim.x + threadIdx.x;
    if (i >= n) return;
    int c = g_cnt[i];
    int base = atomicAdd(&g_total, c);   // contiguous row, arbitrary placement
    g_base[i]   = base;
    g_cursor[i] = base;
    g_dinv[i]   = rsqrtf((float)c + 1.0f);   // deg of A+I
}

// premultiplied edge norm: nrm = dinv[src]*dinv[dst]
__global__ void fill_kernel(const int* __restrict__ src,
                            const int* __restrict__ dst, int E) {
    int e = blockIdx.x * blockDim.x + threadIdx.x;
    if (e >= E) return;
    int d = dst[e];
    int s = src[e];
    int pos = atomicAdd(&g_cursor[d], 1);
    float nrm = g_dinv[s] * g_dinv[d];
    g_csr[pos] = make_int2(s, __float_as_int(nrm));   // one 8B store
}

// ================= f32x2 register-blocked GEMM =================
// 64-row tile, 256 threads, thread = 4 rows x 4 cols. Accumulators are column
// PAIRS in 64-bit regs; W float4 reinterprets as 2 f32x2 operands (no packs);
// A stored pre-duplicated (x,x) in smem. Inner loop: 13 instr / 32 FLOP.
template<int K>
__device__ __forceinline__ void gemm_rb_compute(const float* __restrict__ A,
                                                const float* __restrict__ W,
                                                int n, int row0,
                                                ull* acc01, ull* acc23) {
    __shared__ ull    As_d[64][33];   // duplicated (x,x) pairs, k-chunk 32, pad 1
    __shared__ float4 Ws[32][16];     // W chunk [32 k][64 cols]

    const int t  = threadIdx.x;
    const int tr = (t >> 4) << 2;
    const int tc = t & 15;

    for (int kh = 0; kh < K; kh += 32) {
        // stage W chunk: 512 float4
        #pragma unroll
        for (int i = t; i < 512; i += 256) {
            int k = i >> 4, c = i & 15;
            Ws[k][c] = ((const float4*)(W + (size_t)(kh + k) * HID))[c];
        }
        // stage A chunk duplicated: 64 rows x 8 float4 (32 k-values)
        #pragma unroll
        for (int i = t; i < 512; i += 256) {
            int r = i >> 3, c = i & 7;
            float4 v = make_float4(0.f,0.f,0.f,0.f);
            int row = row0 + r;
            if (row < n) v = *(const float4*)(A + (size_t)row * K + kh + c * 4);
            ull p0, p1, p2, p3;
            PACKDUP(p0, v.x); PACKDUP(p1, v.y);
            PACKDUP(p2, v.z); PACKDUP(p3, v.w);
            As_d[r][c*4+0] = p0; As_d[r][c*4+1] = p1;
            As_d[r][c*4+2] = p2; As_d[r][c*4+3] = p3;
        }
        __syncthreads();

        #pragma unroll 8
        for (int k = 0; k < 32; k++) {
            ulonglong2 w = *(const ulonglong2*)&Ws[k][tc];   // (w0,w1),(w2,w3)
            #pragma unroll
            for (int j = 0; j < 4; j++) {
                ull x = As_d[tr + j][k];                      // (xj, xj)
                FMA2(acc01[j], x, w.x, acc01[j]);
                FMA2(acc23[j], x, w.y, acc23[j]);
            }
        }
        __syncthreads();
    }
}

// feature_pre: x[n,128] @ W_pre + b -> g_h (fp32). Globals referenced in device
// code only (GB300 ATS silently dereferences host-side shadow symbols).
__global__ void gemm_pre_rb_kernel(const float* __restrict__ x,
                                   const float* __restrict__ W,
                                   const float* __restrict__ bias, int n) {
    ull acc01[4] = {0, 0, 0, 0}, acc23[4] = {0, 0, 0, 0};
    int row0 = blockIdx.x * 64;
    gemm_rb_compute<IN_DIM>(x, W, n, row0, acc01, acc23);

    const int tr = (threadIdx.x >> 4) << 2, tc = threadIdx.x & 15;
    float4 b = ((const float4*)bias)[tc];
    #pragma unroll
    for (int j = 0; j < 4; j++) {
        int row = row0 + tr + j;
        if (row < n) {
            float4 r;
            UNPACK2(r.x, r.y, acc01[j]);
            UNPACK2(r.z, r.w, acc23[j]);
            r.x += b.x; r.y += b.y; r.z += b.z; r.w += b.w;
            ((float4*)(g_h + (size_t)row * HID))[tc] = r;
        }
    }
}

// layer GEMM: g_h[n,64] @ W -> g_hw_h (fp16 storage for gather bandwidth)
__global__ void gemm_layer_rb_kernel(const float* __restrict__ W, int n) {
    ull acc01[4] = {0, 0, 0, 0}, acc23[4] = {0, 0, 0, 0};
    int row0 = blockIdx.x * 64;
    gemm_rb_compute<HID>(g_h, W, n, row0, acc01, acc23);

    const int tr = (threadIdx.x >> 4) << 2, tc = threadIdx.x & 15;
    #pragma unroll
    for (int j = 0; j < 4; j++) {
        int row = row0 + tr + j;
        if (row < n) {
            float4 r;
            UNPACK2(r.x, r.y, acc01[j]);
            UNPACK2(r.z, r.w, acc23[j]);
            __half2 h0 = __floats2half2_rn(r.x, r.y);
            __half2 h1 = __floats2half2_rn(r.z, r.w);
            uint2 pack = make_uint2(*reinterpret_cast<const unsigned*>(&h0),
                                    *reinterpret_cast<const unsigned*>(&h1));
            ((uint2*)(g_hw_h + (size_t)row * HID))[tc] = pack;
        }
    }
}

// ================= fused gather (warp per node) — R11-proven ====================
// acc = hw[node]*dinv^2 + b  +  sum_{e: dst=node} hw[src_e] * nrm_e
template<bool FINAL>
__global__ void gather_kernel(const float* __restrict__ bias,
                              float* __restrict__ out, int n) {
    int w    = (blockIdx.x * blockDim.x + threadIdx.x) >> 5;
    int lane = threadIdx.x & 31;
    if (w >= n) return;

    const __half2* hw2 = (const __half2*)g_hw_h;   // row = 32 half2
    float dd = g_dinv[w];
    float2 self = __half22float2(hw2[(size_t)w * 32 + lane]);
    float2 b    = ((const float2*)bias)[lane];
    float2 acc;
    acc.x = self.x * dd * dd + b.x;
    acc.y = self.y * dd * dd + b.y;

    int jbeg = g_base[w];
    int jend = jbeg + g_cnt[w];
    for (int j0 = jbeg; j0 < jend; j0 += 32) {
        int j = j0 + lane;
        int   s  = 0;
        float nm = 0.f;
        if (j < jend) {
            int2 rec = g_csr[j];
            s  = rec.x;
            nm = __int_as_float(rec.y);
        }
        int m = min(32, jend - j0);
        for (int i = 0; i < m; i++) {
            int   si = __shfl_sync(0xffffffffu, s,  i);
            float ni = __shfl_sync(0xffffffffu, nm, i);
            float2 v = __half22float2(hw2[(size_t)si * 32 + lane]);
            acc.x += v.x * ni;
            acc.y += v.y * ni;
        }
    }

    if (!FINAL) {
        float2 r;
        r.x = fmaxf(acc.x, 0.f);
        r.y = fmaxf(acc.y, 0.f);
        ((float2*)g_h)[(size_t)w * 32 + lane] = r;
    } else {
        float ss = acc.x * acc.x + acc.y * acc.y;
        #pragma unroll
        for (int o = 16; o; o >>= 1) ss += __shfl_xor_sync(0xffffffffu, ss, o);
        float sc = 1.0f / fmaxf(sqrtf(ss), 1e-12f);
        float2 r; r.x = acc.x * sc; r.y = acc.y * sc;
        ((float2*)out)[(size_t)w * 32 + lane] = r;
    }
}

// ================= host launcher (forked graph: CSR || GEMM chain) ==============
extern "C" void kernel_launch(void* const* d_in, const int* in_sizes, int n_in,
                              void* d_out, int out_size) {
    const float* x     = (const float*)d_in[0];
    const int*   ei    = (const int*)d_in[1];   // int32 (JAX x64 disabled)
    const float* W_pre = (const float*)d_in[2];
    const float* b_pre = (const float*)d_in[3];
    const float* Wl[3] = {(const float*)d_in[4], (const float*)d_in[6], (const float*)d_in[8]};
    const float* Bl[3] = {(const float*)d_in[5], (const float*)d_in[7], (const float*)d_in[9]};
    float* out = (float*)d_out;

    int n = in_sizes[0] / IN_DIM;    // 100000
    int E = in_sizes[1] / 2;         // 1600000
    const int* src_idx = ei;
    const int* dst_idx = ei + E;

    // lazily-created side stream + fork/join events (first call = correctness run)
    static cudaStream_t s_side = nullptr;
    static cudaEvent_t  s_fork = nullptr, s_join = nullptr;
    if (!s_side) {
        cudaStreamCreateWithFlags(&s_side, cudaStreamNonBlocking);
        cudaEventCreateWithFlags(&s_fork, cudaEventDisableTiming);
        cudaEventCreateWithFlags(&s_join, cudaEventDisableTiming);
    }

    int gemm_blocks   = (n + 63) / 64;
    int gather_blocks = (n * 32 + 255) / 256;

    // ---- fork: CSR build on side stream ----
    cudaEventRecord(s_fork, 0);
    cudaStreamWaitEvent(s_side, s_fork, 0);
    zero_cnt_kernel<<<(n + 255) / 256, 256, 0, s_side>>>(n);
    hist_kernel<<<(E + 255) / 256, 256, 0, s_side>>>(dst_idx, E);
    alloc_base_kernel<<<(n + 255) / 256, 256, 0, s_side>>>(n);
    fill_kernel<<<(E + 255) / 256, 256, 0, s_side>>>(src_idx, dst_idx, E);
    cudaEventRecord(s_join, s_side);

    // ---- main stream: GEMM chain (independent of CSR) ----
    gemm_pre_rb_kernel<<<gemm_blocks, 256>>>(x, W_pre, b_pre, n);
    gemm_layer_rb_kernel<<<gemm_blocks, 256>>>(Wl[0], n);

    // ---- join: gathers need both chains ----
    cudaStreamWaitEvent(0, s_join, 0);

    gather_kernel<false><<<gather_blocks, 256>>>(Bl[0], nullptr, n);
    // layer 2
    gemm_layer_rb_kernel<<<gemm_blocks, 256>>>(Wl[1], n);
    gather_kernel<false><<<gather_blocks, 256>>>(Bl[1], nullptr, n);
    // layer 3 (+ L2 normalize)
    gemm_layer_rb_kernel<<<gemm_blocks, 256>>>(Wl[2], n);
    gather_kernel<true><<<gather_blocks, 256>>>(Bl[2], out, n);
}